// round 6
// baseline (speedup 1.0000x reference)
#include <cuda_runtime.h>
#include <cuda_bf16.h>
#include <math.h>
#include <stdint.h>

// Problem constants (fixed-shape problem)
#define BB 8
#define SS 4096
#define DD 1024
#define KK 1024
#define M_TOTAL (BB * SS)   // 32768
#define NPART 8             // norm column-block partials (N tile = 128)

// ---------------- scratch (device globals: allocation-free) ----------------
__device__ __align__(16) __nv_bfloat16 g_wvt[KK * KK];      // Wv^T in bf16 (2 MB)
__device__ float g_normsq_part[NPART * M_TOTAL];
__device__ float g_fq_part[8 * BB * KK];
__device__ float g_fq[BB * KK];
__device__ float g_c[BB];
__device__ float g_h[BB * DD];
__device__ float g_w[BB * SS];
__device__ float g_u[BB * SS];
__device__ float g_su[BB];
__device__ float g_t_part[8 * BB * DD];
__device__ float g_seed_part[8 * BB * KK];

// ================= baseline-PTX helpers (compute_103-safe) =================
__device__ __forceinline__ uint32_t smem_u32(const void* p) {
    uint32_t a;
    asm("{ .reg .u64 t; cvta.to.shared.u64 t, %1; cvt.u32.u64 %0, t; }" : "=r"(a) : "l"(p));
    return a;
}
__device__ __forceinline__ void cp_async16(uint32_t saddr, const void* gaddr) {
    asm volatile("cp.async.cg.shared.global [%0], [%1], 16;" :: "r"(saddr), "l"(gaddr) : "memory");
}
__device__ __forceinline__ void cp_commit() {
    asm volatile("cp.async.commit_group;" ::: "memory");
}
template <int N>
__device__ __forceinline__ void cp_wait() {
    asm volatile("cp.async.wait_group %0;" :: "n"(N) : "memory");
}
__device__ __forceinline__ void ldm_x4(uint32_t& r0, uint32_t& r1, uint32_t& r2, uint32_t& r3,
                                       uint32_t addr) {
    asm volatile("ldmatrix.sync.aligned.m8n8.x4.shared.b16 {%0,%1,%2,%3}, [%4];"
                 : "=r"(r0), "=r"(r1), "=r"(r2), "=r"(r3) : "r"(addr));
}
__device__ __forceinline__ uint32_t pack_bf16x2(float lo, float hi) {
    uint32_t d;
    asm("cvt.rn.bf16x2.f32 %0, %1, %2;" : "=r"(d) : "f"(hi), "f"(lo));
    return d;
}
__device__ __forceinline__ void mma16816(float& c0, float& c1, float& c2, float& c3,
                                         uint32_t a0, uint32_t a1, uint32_t a2, uint32_t a3,
                                         uint32_t b0, uint32_t b1) {
    asm volatile(
        "mma.sync.aligned.m16n8k16.row.col.f32.bf16.bf16.f32 "
        "{%0,%1,%2,%3}, {%4,%5,%6,%7}, {%8,%9}, {%0,%1,%2,%3};"
        : "+f"(c0), "+f"(c1), "+f"(c2), "+f"(c3)
        : "r"(a0), "r"(a1), "r"(a2), "r"(a3), "r"(b0), "r"(b1));
}

// ---------------- threefry-2x32 core ----------------
__device__ __forceinline__ uint32_t rotl32(uint32_t x, int d) {
    return (x << d) | (x >> (32 - d));
}
__device__ uint2 threefry2x32(uint32_t k0, uint32_t k1, uint32_t x0, uint32_t x1) {
    uint32_t k2 = k0 ^ k1 ^ 0x1BD11BDAu;
    x0 += k0; x1 += k1;
#define TF_RND(r) { x0 += x1; x1 = rotl32(x1, (r)); x1 ^= x0; }
    TF_RND(13) TF_RND(15) TF_RND(26) TF_RND(6)
    x0 += k1; x1 += k2 + 1u;
    TF_RND(17) TF_RND(29) TF_RND(16) TF_RND(24)
    x0 += k2; x1 += k0 + 2u;
    TF_RND(13) TF_RND(15) TF_RND(26) TF_RND(6)
    x0 += k0; x1 += k1 + 3u;
    TF_RND(17) TF_RND(29) TF_RND(16) TF_RND(24)
    x0 += k1; x1 += k2 + 4u;
    TF_RND(13) TF_RND(15) TF_RND(26) TF_RND(6)
    x0 += k2; x1 += k0 + 5u;
#undef TF_RND
    return make_uint2(x0, x1);
}

// ---------------- K1: fq partials ----------------
__global__ void k1_fq_part(const float* __restrict__ q, const float* __restrict__ wq_w) {
    int kc = blockIdx.x, b = blockIdx.y, j = threadIdx.x;
    __shared__ float qs[128];
    if (j < 128) qs[j] = q[b * DD + kc * 128 + j];
    __syncthreads();
    float acc = 0.0f;
    int dbase = kc * 128;
#pragma unroll 8
    for (int dd = 0; dd < 128; dd++)
        acc += qs[dd] * wq_w[(size_t)(dbase + dd) * KK + j];
    g_fq_part[(kc * BB + b) * KK + j] = acc;
}

// ---------------- K1b: reduce fq + c[b] = fq . bk ----------------
__global__ void k1b_fq_reduce(const float* __restrict__ wq_b, const float* __restrict__ wk_b) {
    int b = blockIdx.x, j = threadIdx.x;
    float v = wq_b[j];
#pragma unroll
    for (int p = 0; p < 8; p++) v += g_fq_part[(p * BB + b) * KK + j];
    g_fq[b * KK + j] = v;

    float t = v * wk_b[j];
    __shared__ float red[32];
#pragma unroll
    for (int o = 16; o; o >>= 1) t += __shfl_down_sync(0xffffffffu, t, o);
    if ((j & 31) == 0) red[j >> 5] = t;
    __syncthreads();
    if (j < 32) {
        float s = red[j];
#pragma unroll
        for (int o = 16; o; o >>= 1) s += __shfl_down_sync(0xffffffffu, s, o);
        if (j == 0) g_c[b] = s;
    }
}

// ---------------- K2: h[b,d] = Wk[d,:] . fq[b,:] ----------------
__global__ void k2_h(const float* __restrict__ wk_w) {
    int wg = blockIdx.x * 8 + (threadIdx.x >> 5);
    int lane = threadIdx.x & 31;
    int b = wg >> 10, d = wg & 1023;
    const float4* row4 = (const float4*)(wk_w + (size_t)d * KK);
    const float4* fq4 = (const float4*)(g_fq + b * KK);
    float acc = 0.0f;
#pragma unroll 2
    for (int i = lane; i < 256; i += 32) {
        float4 a = row4[i]; float4 f = fq4[i];
        acc += a.x * f.x + a.y * f.y + a.z * f.z + a.w * f.w;
    }
#pragma unroll
    for (int o = 16; o; o >>= 1) acc += __shfl_down_sync(0xffffffffu, acc, o);
    if (lane == 0) g_h[b * DD + d] = acc;
}

// ---------------- K3: attention weights ----------------
__global__ void k3_weights(const float* __restrict__ kmat, float* __restrict__ out_w) {
    int wg = blockIdx.x * 8 + (threadIdx.x >> 5);
    int lane = threadIdx.x & 31;
    int b = wg / SS;
    const float4* kr4 = (const float4*)(kmat + (size_t)wg * DD);
    const float4* h4 = (const float4*)(g_h + b * DD);
    float acc = 0.0f;
#pragma unroll 2
    for (int i = lane; i < 256; i += 32) {
        float4 a = kr4[i]; float4 hh = h4[i];
        acc += a.x * hh.x + a.y * hh.y + a.z * hh.z + a.w * hh.w;
    }
#pragma unroll
    for (int o = 16; o; o >>= 1) acc += __shfl_down_sync(0xffffffffu, acc, o);
    if (lane == 0) {
        float logit = (acc + g_c[b]) * 0.03125f;
        float w = 1.0f / (1.0f + expf(-logit));
        g_w[wg] = w;
        out_w[wg] = w;
    }
}

// ---------------- conv_wvt: Wv [k][n] fp32 -> Wv^T [n][k] bf16 ----------------
__global__ void conv_wvt(const float* __restrict__ wv) {
    __shared__ float s[32][33];
    int kt = blockIdx.x, nt = blockIdx.y;
    int tx = threadIdx.x, ty = threadIdx.y;   // 32 x 8
#pragma unroll
    for (int j = 0; j < 32; j += 8)
        s[ty + j][tx] = wv[(size_t)(kt * 32 + ty + j) * KK + nt * 32 + tx];
    __syncthreads();
#pragma unroll
    for (int j = 0; j < 32; j += 8)
        g_wvt[(size_t)(nt * 32 + ty + j) * KK + kt * 32 + tx] = __float2bfloat16(s[tx][ty + j]);
}

// ---------------- K4: bf16 mma.sync GEMM (fp32 A in-kernel convert) -> row sumsq ----------------
// Block tile 128(M) x 128(N), K chunks of 32, 3-stage cp.async pipeline.
// A: fp32 staged in smem, fragments built via LDS.64 + cvt.bf16x2.
// B: bf16 (g_wvt) staged in smem, ldmatrix.
#define KCH 32
#define ITERS (KK / KCH)       // 32
#define STA_ROWF 36            // fp32 A staging row stride (floats) = 144B, 16B-aligned
#define STA_BYTES (128 * STA_ROWF * 4)   // 18432 per stage
#define ROWB 80                // bf16 B smem row stride bytes (64B data + 16B pad)
#define STB_BYTES (128 * ROWB)           // 10240 per stage
#define STA_OFF 0
#define STB_OFF (3 * STA_BYTES)          // 55296
#define BS_OFF  (STB_OFF + 3 * STB_BYTES)  // 86016
#define RSUM_OFF (BS_OFF + 512)            // 86528
#define K4_SMEM (RSUM_OFF + 1024)          // 87552

__global__ void __launch_bounds__(256, 2) k4_mma(
    const float* __restrict__ Vmat, const float* __restrict__ bv) {
    extern __shared__ __align__(16) char smem[];
    float* bs = (float*)(smem + BS_OFF);
    float (*rsum)[2] = (float (*)[2])(smem + RSUM_OFF);

    const int tid = threadIdx.x;
    const int wid = tid >> 5;
    const int lane = tid & 31;
    const int warpM = wid >> 1;
    const int warpN = wid & 1;
    const int bn = blockIdx.x;
    const int bm = blockIdx.y;
    const int row0 = bm * 128;
    const int col0 = bn * 128;

    if (tid < 128) bs[tid] = bv[col0 + tid];

    // copy-thread mapping: 2 threads per row
    const int cr = tid >> 1;      // 0..127
    const int cq = tid & 1;
    const float* Arow = Vmat + (size_t)(row0 + cr) * KK;          // fp32 row
    const uint4* Brow = (const uint4*)g_wvt + (size_t)(col0 + cr) * 128;  // bf16 row as uint4

    const uint32_t sbase = smem_u32(smem);
    const uint32_t staB[3] = { sbase + STA_OFF,
                               sbase + STA_OFF + STA_BYTES,
                               sbase + STA_OFF + 2 * STA_BYTES };
    const uint32_t stbB[3] = { sbase + STB_OFF,
                               sbase + STB_OFF + STB_BYTES,
                               sbase + STB_OFF + 2 * STB_BYTES };

    // issue loads for chunk i into stage st
    auto issue = [&](int i, int st) {
        const uint32_t adst = staB[st] + cr * (STA_ROWF * 4) + cq * 64;
        const float* asrc = Arow + i * KCH + cq * 16;
#pragma unroll
        for (int j = 0; j < 4; j++)
            cp_async16(adst + j * 16, asrc + j * 4);
        const uint32_t bdst = stbB[st] + cr * ROWB + cq * 32;
        const uint4* bsrc = Brow + i * 4 + cq * 2;
#pragma unroll
        for (int j = 0; j < 2; j++)
            cp_async16(bdst + j * 16, bsrc + j);
        cp_commit();
    };

    float acc[2][8][4];
#pragma unroll
    for (int mi = 0; mi < 2; mi++)
#pragma unroll
        for (int ni = 0; ni < 8; ni++)
#pragma unroll
            for (int c = 0; c < 4; c++) acc[mi][ni][c] = 0.0f;

    issue(0, 0);
    issue(1, 1);

    // fragment lane addressing
    const int g = lane >> 2;
    const int tc = lane & 3;
    const int b_nrow = warpN * 64 + ((lane >> 4) & 1) * 8 + (lane & 7);
    const int b_koff = ((lane >> 3) & 1) * 16;

    for (int i = 0; i < ITERS; i++) {
        if (i == ITERS - 1) cp_wait<0>(); else cp_wait<1>();
        __syncthreads();
        if (i + 2 < ITERS) issue(i + 2, (i + 2) % 3);

        const int cur = i % 3;
        const float* stA = (const float*)(smem + (size_t)STA_OFF + cur * STA_BYTES);
        const uint32_t cB = stbB[cur];

#pragma unroll
        for (int kk = 0; kk < 2; kk++) {
            // A fragments: m16n8k16 layout, built from fp32 staging
            uint32_t a[2][4];
#pragma unroll
            for (int mi = 0; mi < 2; mi++) {
                const float* p = stA + (warpM * 32 + mi * 16 + g) * STA_ROWF + kk * 16 + tc * 2;
                float2 v0 = *(const float2*)p;                      // (g, 2tc)
                float2 v1 = *(const float2*)(p + 8 * STA_ROWF);     // (g+8, 2tc)
                float2 v2 = *(const float2*)(p + 8);                // (g, 2tc+8)
                float2 v3 = *(const float2*)(p + 8 * STA_ROWF + 8); // (g+8, 2tc+8)
                a[mi][0] = pack_bf16x2(v0.x, v0.y);
                a[mi][1] = pack_bf16x2(v1.x, v1.y);
                a[mi][2] = pack_bf16x2(v2.x, v2.y);
                a[mi][3] = pack_bf16x2(v3.x, v3.y);
            }
            uint32_t b[8][2];
#pragma unroll
            for (int np = 0; np < 4; np++) {
                uint32_t t0, t1, t2, t3;
                ldm_x4(t0, t1, t2, t3,
                       cB + (b_nrow + np * 16) * ROWB + kk * 32 + b_koff);
                b[np * 2 + 0][0] = t0; b[np * 2 + 0][1] = t1;
                b[np * 2 + 1][0] = t2; b[np * 2 + 1][1] = t3;
            }
#pragma unroll
            for (int mi = 0; mi < 2; mi++)
#pragma unroll
                for (int ni = 0; ni < 8; ni++)
                    mma16816(acc[mi][ni][0], acc[mi][ni][1], acc[mi][ni][2], acc[mi][ni][3],
                             a[mi][0], a[mi][1], a[mi][2], a[mi][3],
                             b[ni][0], b[ni][1]);
        }
    }
    __syncthreads();

    // epilogue: bias + per-row sumsq
    float sums[4] = {0.0f, 0.0f, 0.0f, 0.0f};
    const int cbase = warpN * 64 + tc * 2;
#pragma unroll
    for (int mi = 0; mi < 2; mi++) {
#pragma unroll
        for (int ni = 0; ni < 8; ni++) {
            const float b0 = bs[cbase + ni * 8];
            const float b1 = bs[cbase + ni * 8 + 1];
            float x0 = acc[mi][ni][0] + b0;
            float x1 = acc[mi][ni][1] + b1;
            float x2 = acc[mi][ni][2] + b0;
            float x3 = acc[mi][ni][3] + b1;
            sums[mi * 2 + 0] += x0 * x0 + x1 * x1;
            sums[mi * 2 + 1] += x2 * x2 + x3 * x3;
        }
    }
#pragma unroll
    for (int j = 0; j < 4; j++) {
        sums[j] += __shfl_xor_sync(0xffffffffu, sums[j], 1);
        sums[j] += __shfl_xor_sync(0xffffffffu, sums[j], 2);
    }
    if (tc == 0) {
#pragma unroll
        for (int j = 0; j < 4; j++) {
            const int rl = warpM * 32 + (j >> 1) * 16 + (j & 1) * 8 + g;
            rsum[rl][warpN] = sums[j];
        }
    }
    __syncthreads();
    if (tid < 128)
        g_normsq_part[bn * M_TOTAL + row0 + tid] = rsum[tid][0] + rsum[tid][1];
}

// ---------------- K4b: u = w / max(1, ||fv||); su[b] = sum u ----------------
__global__ void k4b_u() {
    int b = blockIdx.x, tid = threadIdx.x;
    float local = 0.0f;
    for (int s = tid; s < SS; s += 1024) {
        int row = b * SS + s;
        float ns = 0.0f;
#pragma unroll
        for (int p = 0; p < NPART; p++) ns += g_normsq_part[p * M_TOTAL + row];
        float u = g_w[row] / fmaxf(1.0f, sqrtf(ns));
        g_u[row] = u;
        local += u;
    }
    __shared__ float red[32];
#pragma unroll
    for (int o = 16; o; o >>= 1) local += __shfl_down_sync(0xffffffffu, local, o);
    if ((tid & 31) == 0) red[tid >> 5] = local;
    __syncthreads();
    if (tid < 32) {
        float s2 = red[tid];
#pragma unroll
        for (int o = 16; o; o >>= 1) s2 += __shfl_down_sync(0xffffffffu, s2, o);
        if (tid == 0) g_su[b] = s2;
    }
}

// ---------------- K5: t[b,d] = sum_s u * v[b,s,d] (fp32 path) ----------------
__global__ void k5_t(const float* __restrict__ Vmat) {
    int dc = blockIdx.x, b = blockIdx.y, sc = blockIdx.z;
    int tid = threadIdx.x;
    int d = dc * 128 + tid;
    __shared__ float ush[128];
    float acc = 0.0f;
    int sbase = sc * 512;
    for (int s0 = sbase; s0 < sbase + 512; s0 += 128) {
        ush[tid] = g_u[b * SS + s0 + tid];
        __syncthreads();
        const float* base = Vmat + (size_t)(b * SS + s0) * DD + d;
#pragma unroll 8
        for (int i = 0; i < 128; i++) acc += ush[i] * base[(size_t)i * DD];
        __syncthreads();
    }
    g_t_part[(sc * BB + b) * DD + d] = acc;
}

// ---------------- K6: seed partials: t[b,:] @ Wv ----------------
__global__ void k6_seed_part(const float* __restrict__ wv_w) {
    int b = blockIdx.x, dc = blockIdx.y, j = threadIdx.x;
    __shared__ float ts[128];
    if (j < 128) {
        float s = 0.0f;
#pragma unroll
        for (int sc = 0; sc < 8; sc++) s += g_t_part[(sc * BB + b) * DD + dc * 128 + j];
        ts[j] = s;
    }
    __syncthreads();
    float acc = 0.0f;
    int dbase = dc * 128;
#pragma unroll 8
    for (int dd = 0; dd < 128; dd++)
        acc += ts[dd] * wv_w[(size_t)(dbase + dd) * KK + j];
    g_seed_part[(dc * BB + b) * KK + j] = acc;
}

// ---------------- K7: reduce + threefry noise (partitionable) ----------------
__global__ void k7_final(const float* __restrict__ wv_b, float* __restrict__ out_seed) {
    int i = blockIdx.x * 256 + threadIdx.x;
    int b = i >> 10, j = i & 1023;
    float v = 0.0f;
#pragma unroll
    for (int p = 0; p < 8; p++) v += g_seed_part[(p * BB + b) * KK + j];
    v += g_su[b] * wv_b[j];

    uint2 r = threefry2x32(0u, 1234u, 0u, (uint32_t)i);
    uint32_t bits = r.x ^ r.y;
    float f = __uint_as_float((bits >> 9) | 0x3f800000u) - 1.0f;
    const float lo = -0.99999994f;
    float u = fmaxf(lo, f * 2.0f + lo);
    float n = 1.41421356237309515f * erfinvf(u);

    out_seed[i] = v + n * 0.1f;
}

// ---------------- launch ----------------
extern "C" void kernel_launch(void* const* d_in, const int* in_sizes, int n_in,
                              void* d_out, int out_size) {
    const float* q    = (const float*)d_in[0];
    const float* kmat = (const float*)d_in[1];
    const float* vmat = (const float*)d_in[2];
    const float* wq_w = (const float*)d_in[3];
    const float* wq_b = (const float*)d_in[4];
    const float* wk_w = (const float*)d_in[5];
    const float* wk_b = (const float*)d_in[6];
    const float* wv_w = (const float*)d_in[7];
    const float* wv_b = (const float*)d_in[8];
    float* out = (float*)d_out;    // [0,8192): seed, [8192,40960): attention weights

    cudaFuncSetAttribute(k4_mma, cudaFuncAttributeMaxDynamicSharedMemorySize, K4_SMEM);

    conv_wvt<<<dim3(32, 32), dim3(32, 8)>>>(wv_w);
    k1_fq_part<<<dim3(8, 8), 1024>>>(q, wq_w);
    k1b_fq_reduce<<<8, 1024>>>(wq_b, wk_b);
    k2_h<<<1024, 256>>>(wk_w);
    k3_weights<<<4096, 256>>>(kmat, out + BB * KK);
    k4_mma<<<dim3(NPART, 256), 256, K4_SMEM>>>(vmat, wv_b);
    k4b_u<<<8, 1024>>>();
    k5_t<<<dim3(8, 8, 8), 128>>>(vmat);
    k6_seed_part<<<dim3(8, 8), 1024>>>(wv_w);
    k7_final<<<32, 256>>>(wv_b, out);
}

// round 7
// speedup vs baseline: 1.7415x; 1.7415x over previous
#include <cuda_runtime.h>
#include <cuda_bf16.h>
#include <math.h>
#include <stdint.h>

// Problem constants (fixed-shape problem)
#define BB 8
#define SS 4096
#define DD 1024
#define KK 1024
#define M_TOTAL (BB * SS)   // 32768
#define NPART 8             // norm column-block partials (N tile = 128)

// ---------------- scratch (device globals: allocation-free) ----------------
__device__ uint4 g_vbf4[(size_t)M_TOTAL * KK / 8];          // V in bf16 (67 MB)
__device__ __align__(16) __nv_bfloat16 g_wvt[KK * KK];      // Wv^T in bf16 (2 MB)
__device__ float g_normsq_part[NPART * M_TOTAL];
__device__ float g_fq_part[8 * BB * KK];
__device__ float g_fq[BB * KK];
__device__ float g_c[BB];
__device__ float g_h[BB * DD];
__device__ float g_w[BB * SS];
__device__ float g_u[BB * SS];
__device__ float g_su[BB];
__device__ float g_t_part[8 * BB * DD];
__device__ float g_seed_part[8 * BB * KK];

// ================= baseline-PTX helpers (compute_103-safe) =================
__device__ __forceinline__ uint32_t smem_u32(const void* p) {
    uint32_t a;
    asm("{ .reg .u64 t; cvta.to.shared.u64 t, %1; cvt.u32.u64 %0, t; }" : "=r"(a) : "l"(p));
    return a;
}
__device__ __forceinline__ void cp_async16(uint32_t saddr, const void* gaddr) {
    asm volatile("cp.async.cg.shared.global [%0], [%1], 16;" :: "r"(saddr), "l"(gaddr) : "memory");
}
__device__ __forceinline__ void cp_commit() {
    asm volatile("cp.async.commit_group;" ::: "memory");
}
template <int N>
__device__ __forceinline__ void cp_wait() {
    asm volatile("cp.async.wait_group %0;" :: "n"(N) : "memory");
}
__device__ __forceinline__ void ldm_x4(uint32_t& r0, uint32_t& r1, uint32_t& r2, uint32_t& r3,
                                       uint32_t addr) {
    asm volatile("ldmatrix.sync.aligned.m8n8.x4.shared.b16 {%0,%1,%2,%3}, [%4];"
                 : "=r"(r0), "=r"(r1), "=r"(r2), "=r"(r3) : "r"(addr));
}
__device__ __forceinline__ void mma16816(float& c0, float& c1, float& c2, float& c3,
                                         uint32_t a0, uint32_t a1, uint32_t a2, uint32_t a3,
                                         uint32_t b0, uint32_t b1) {
    asm volatile(
        "mma.sync.aligned.m16n8k16.row.col.f32.bf16.bf16.f32 "
        "{%0,%1,%2,%3}, {%4,%5,%6,%7}, {%8,%9}, {%0,%1,%2,%3};"
        : "+f"(c0), "+f"(c1), "+f"(c2), "+f"(c3)
        : "r"(a0), "r"(a1), "r"(a2), "r"(a3), "r"(b0), "r"(b1));
}

// ---------------- threefry-2x32 core ----------------
__device__ __forceinline__ uint32_t rotl32(uint32_t x, int d) {
    return (x << d) | (x >> (32 - d));
}
__device__ uint2 threefry2x32(uint32_t k0, uint32_t k1, uint32_t x0, uint32_t x1) {
    uint32_t k2 = k0 ^ k1 ^ 0x1BD11BDAu;
    x0 += k0; x1 += k1;
#define TF_RND(r) { x0 += x1; x1 = rotl32(x1, (r)); x1 ^= x0; }
    TF_RND(13) TF_RND(15) TF_RND(26) TF_RND(6)
    x0 += k1; x1 += k2 + 1u;
    TF_RND(17) TF_RND(29) TF_RND(16) TF_RND(24)
    x0 += k2; x1 += k0 + 2u;
    TF_RND(13) TF_RND(15) TF_RND(26) TF_RND(6)
    x0 += k0; x1 += k1 + 3u;
    TF_RND(17) TF_RND(29) TF_RND(16) TF_RND(24)
    x0 += k1; x1 += k2 + 4u;
    TF_RND(13) TF_RND(15) TF_RND(26) TF_RND(6)
    x0 += k2; x1 += k0 + 5u;
#undef TF_RND
    return make_uint2(x0, x1);
}

// ---------------- K1: fq partials ----------------
__global__ void k1_fq_part(const float* __restrict__ q, const float* __restrict__ wq_w) {
    int kc = blockIdx.x, b = blockIdx.y, j = threadIdx.x;
    __shared__ float qs[128];
    if (j < 128) qs[j] = q[b * DD + kc * 128 + j];
    __syncthreads();
    float acc = 0.0f;
    int dbase = kc * 128;
#pragma unroll 8
    for (int dd = 0; dd < 128; dd++)
        acc += qs[dd] * wq_w[(size_t)(dbase + dd) * KK + j];
    g_fq_part[(kc * BB + b) * KK + j] = acc;
}

// ---------------- K1b: reduce fq + c[b] = fq . bk ----------------
__global__ void k1b_fq_reduce(const float* __restrict__ wq_b, const float* __restrict__ wk_b) {
    int b = blockIdx.x, j = threadIdx.x;
    float v = wq_b[j];
#pragma unroll
    for (int p = 0; p < 8; p++) v += g_fq_part[(p * BB + b) * KK + j];
    g_fq[b * KK + j] = v;

    float t = v * wk_b[j];
    __shared__ float red[32];
#pragma unroll
    for (int o = 16; o; o >>= 1) t += __shfl_down_sync(0xffffffffu, t, o);
    if ((j & 31) == 0) red[j >> 5] = t;
    __syncthreads();
    if (j < 32) {
        float s = red[j];
#pragma unroll
        for (int o = 16; o; o >>= 1) s += __shfl_down_sync(0xffffffffu, s, o);
        if (j == 0) g_c[b] = s;
    }
}

// ---------------- K2: h[b,d] = Wk[d,:] . fq[b,:] ----------------
__global__ void k2_h(const float* __restrict__ wk_w) {
    int wg = blockIdx.x * 8 + (threadIdx.x >> 5);
    int lane = threadIdx.x & 31;
    int b = wg >> 10, d = wg & 1023;
    const float4* row4 = (const float4*)(wk_w + (size_t)d * KK);
    const float4* fq4 = (const float4*)(g_fq + b * KK);
    float acc = 0.0f;
#pragma unroll 2
    for (int i = lane; i < 256; i += 32) {
        float4 a = row4[i]; float4 f = fq4[i];
        acc += a.x * f.x + a.y * f.y + a.z * f.z + a.w * f.w;
    }
#pragma unroll
    for (int o = 16; o; o >>= 1) acc += __shfl_down_sync(0xffffffffu, acc, o);
    if (lane == 0) g_h[b * DD + d] = acc;
}

// ---------------- K3: attention weights ----------------
__global__ void k3_weights(const float* __restrict__ kmat, float* __restrict__ out_w) {
    int wg = blockIdx.x * 8 + (threadIdx.x >> 5);
    int lane = threadIdx.x & 31;
    int b = wg / SS;
    const float4* kr4 = (const float4*)(kmat + (size_t)wg * DD);
    const float4* h4 = (const float4*)(g_h + b * DD);
    float acc = 0.0f;
#pragma unroll 2
    for (int i = lane; i < 256; i += 32) {
        float4 a = kr4[i]; float4 hh = h4[i];
        acc += a.x * hh.x + a.y * hh.y + a.z * hh.z + a.w * hh.w;
    }
#pragma unroll
    for (int o = 16; o; o >>= 1) acc += __shfl_down_sync(0xffffffffu, acc, o);
    if (lane == 0) {
        float logit = (acc + g_c[b]) * 0.03125f;
        float w = 1.0f / (1.0f + expf(-logit));
        g_w[wg] = w;
        out_w[wg] = w;
    }
}

// ---------------- conv_v: V fp32 -> bf16 ----------------
__global__ void conv_v(const float4* __restrict__ v) {
    size_t i = (size_t)blockIdx.x * 256 + threadIdx.x;   // 4194304 uint4 outputs
    float4 a = v[2 * i];
    float4 b = v[2 * i + 1];
    __nv_bfloat162 h0 = __floats2bfloat162_rn(a.x, a.y);
    __nv_bfloat162 h1 = __floats2bfloat162_rn(a.z, a.w);
    __nv_bfloat162 h2 = __floats2bfloat162_rn(b.x, b.y);
    __nv_bfloat162 h3 = __floats2bfloat162_rn(b.z, b.w);
    uint4 o;
    o.x = *reinterpret_cast<uint32_t*>(&h0);
    o.y = *reinterpret_cast<uint32_t*>(&h1);
    o.z = *reinterpret_cast<uint32_t*>(&h2);
    o.w = *reinterpret_cast<uint32_t*>(&h3);
    g_vbf4[i] = o;
}

// ---------------- conv_wvt: Wv [k][n] fp32 -> Wv^T [n][k] bf16 ----------------
__global__ void conv_wvt(const float* __restrict__ wv) {
    __shared__ float s[32][33];
    int kt = blockIdx.x, nt = blockIdx.y;
    int tx = threadIdx.x, ty = threadIdx.y;   // 32 x 8
#pragma unroll
    for (int j = 0; j < 32; j += 8)
        s[ty + j][tx] = wv[(size_t)(kt * 32 + ty + j) * KK + nt * 32 + tx];
    __syncthreads();
#pragma unroll
    for (int j = 0; j < 32; j += 8)
        g_wvt[(size_t)(nt * 32 + ty + j) * KK + kt * 32 + tx] = __float2bfloat16(s[tx][ty + j]);
}

// ---------------- K4: bf16 mma.sync GEMM -> row sumsq partials ----------------
// Block tile 128(M) x 128(N), K chunks of 32, 3-stage cp.async ring,
// ONE __syncthreads per chunk. 8 warps: warpM = wid>>1, warpN = wid&1.
#define KCH 32
#define ITERS (KK / KCH)                 // 32
#define ROWB 80                          // smem row stride bytes (64B data + 16B pad)
#define STG_BYTES (128 * ROWB)           // 10240 per stage per matrix
#define SA_OFF 0
#define SB_OFF (3 * STG_BYTES)           // 30720
#define BS_OFF (6 * STG_BYTES)           // 61440
#define RSUM_OFF (BS_OFF + 512)          // 61952
#define K4_SMEM (RSUM_OFF + 1024)        // 62976

__global__ void __launch_bounds__(256, 2) k4_mma(const float* __restrict__ bv) {
    extern __shared__ __align__(16) char smem[];
    float* bs = (float*)(smem + BS_OFF);
    float (*rsum)[2] = (float (*)[2])(smem + RSUM_OFF);

    const int tid = threadIdx.x;
    const int wid = tid >> 5;
    const int lane = tid & 31;
    const int warpM = wid >> 1;
    const int warpN = wid & 1;
    const int bn = blockIdx.x;
    const int bm = blockIdx.y;
    const int row0 = bm * 128;
    const int col0 = bn * 128;

    if (tid < 128) bs[tid] = bv[col0 + tid];

    const uint4* Ag = g_vbf4 + (size_t)row0 * 128;                  // bf16 rows, 128 uint4 each
    const uint4* Bg = (const uint4*)g_wvt + (size_t)col0 * 128;

    const uint32_t sbase = smem_u32(smem);

    // each thread copies 2 x 16B for A and 2 x 16B for B per chunk
    const int e0 = tid;          // 0..255
    const int e1 = tid + 256;    // 256..511
    const int r0e = e0 >> 2, s0e = e0 & 3;
    const int r1e = e1 >> 2, s1e = e1 & 3;

    auto issue = [&](int i, int st) {
        const uint32_t dA = sbase + SA_OFF + st * STG_BYTES;
        const uint32_t dB = sbase + SB_OFF + st * STG_BYTES;
        const int kseg = i * 4;
        cp_async16(dA + r0e * ROWB + s0e * 16, &Ag[(size_t)r0e * 128 + kseg + s0e]);
        cp_async16(dA + r1e * ROWB + s1e * 16, &Ag[(size_t)r1e * 128 + kseg + s1e]);
        cp_async16(dB + r0e * ROWB + s0e * 16, &Bg[(size_t)r0e * 128 + kseg + s0e]);
        cp_async16(dB + r1e * ROWB + s1e * 16, &Bg[(size_t)r1e * 128 + kseg + s1e]);
        cp_commit();
    };

    float acc[2][8][4];
#pragma unroll
    for (int mi = 0; mi < 2; mi++)
#pragma unroll
        for (int ni = 0; ni < 8; ni++)
#pragma unroll
            for (int c = 0; c < 4; c++) acc[mi][ni][c] = 0.0f;

    issue(0, 0);
    issue(1, 1);

    // ldmatrix lane addressing
    const int a_row = warpM * 32 + (lane & 15);
    const int a_koff = (lane >> 4) * 16;
    const int b_nrow = warpN * 64 + ((lane >> 4) & 1) * 8 + (lane & 7);
    const int b_koff = ((lane >> 3) & 1) * 16;

    for (int i = 0; i < ITERS; i++) {
        if (i == ITERS - 1) cp_wait<0>(); else cp_wait<1>();
        __syncthreads();
        if (i + 2 < ITERS) issue(i + 2, (i + 2) % 3);

        const int cur = i % 3;
        const uint32_t cA = sbase + SA_OFF + cur * STG_BYTES;
        const uint32_t cB = sbase + SB_OFF + cur * STG_BYTES;
#pragma unroll
        for (int kk = 0; kk < 2; kk++) {
            uint32_t a[2][4];
#pragma unroll
            for (int mi = 0; mi < 2; mi++)
                ldm_x4(a[mi][0], a[mi][1], a[mi][2], a[mi][3],
                       cA + (a_row + mi * 16) * ROWB + kk * 32 + a_koff);
            uint32_t b[8][2];
#pragma unroll
            for (int np = 0; np < 4; np++) {
                uint32_t t0, t1, t2, t3;
                ldm_x4(t0, t1, t2, t3,
                       cB + (b_nrow + np * 16) * ROWB + kk * 32 + b_koff);
                b[np * 2 + 0][0] = t0; b[np * 2 + 0][1] = t1;
                b[np * 2 + 1][0] = t2; b[np * 2 + 1][1] = t3;
            }
#pragma unroll
            for (int mi = 0; mi < 2; mi++)
#pragma unroll
                for (int ni = 0; ni < 8; ni++)
                    mma16816(acc[mi][ni][0], acc[mi][ni][1], acc[mi][ni][2], acc[mi][ni][3],
                             a[mi][0], a[mi][1], a[mi][2], a[mi][3],
                             b[ni][0], b[ni][1]);
        }
    }
    __syncthreads();

    // epilogue: bias + per-row sumsq
    float sums[4] = {0.0f, 0.0f, 0.0f, 0.0f};
    const int cbase = warpN * 64 + (lane & 3) * 2;
#pragma unroll
    for (int mi = 0; mi < 2; mi++) {
#pragma unroll
        for (int ni = 0; ni < 8; ni++) {
            const float b0 = bs[cbase + ni * 8];
            const float b1 = bs[cbase + ni * 8 + 1];
            float x0 = acc[mi][ni][0] + b0;
            float x1 = acc[mi][ni][1] + b1;
            float x2 = acc[mi][ni][2] + b0;
            float x3 = acc[mi][ni][3] + b1;
            sums[mi * 2 + 0] += x0 * x0 + x1 * x1;
            sums[mi * 2 + 1] += x2 * x2 + x3 * x3;
        }
    }
#pragma unroll
    for (int j = 0; j < 4; j++) {
        sums[j] += __shfl_xor_sync(0xffffffffu, sums[j], 1);
        sums[j] += __shfl_xor_sync(0xffffffffu, sums[j], 2);
    }
    if ((lane & 3) == 0) {
        const int g = lane >> 2;
#pragma unroll
        for (int j = 0; j < 4; j++) {
            const int rl = warpM * 32 + (j >> 1) * 16 + (j & 1) * 8 + g;
            rsum[rl][warpN] = sums[j];
        }
    }
    __syncthreads();
    if (tid < 128)
        g_normsq_part[bn * M_TOTAL + row0 + tid] = rsum[tid][0] + rsum[tid][1];
}

// ---------------- K4b: u = w / max(1, ||fv||); su[b] = sum u ----------------
__global__ void k4b_u() {
    int b = blockIdx.x, tid = threadIdx.x;
    float local = 0.0f;
    for (int s = tid; s < SS; s += 1024) {
        int row = b * SS + s;
        float ns = 0.0f;
#pragma unroll
        for (int p = 0; p < NPART; p++) ns += g_normsq_part[p * M_TOTAL + row];
        float u = g_w[row] / fmaxf(1.0f, sqrtf(ns));
        g_u[row] = u;
        local += u;
    }
    __shared__ float red[32];
#pragma unroll
    for (int o = 16; o; o >>= 1) local += __shfl_down_sync(0xffffffffu, local, o);
    if ((tid & 31) == 0) red[tid >> 5] = local;
    __syncthreads();
    if (tid < 32) {
        float s2 = red[tid];
#pragma unroll
        for (int o = 16; o; o >>= 1) s2 += __shfl_down_sync(0xffffffffu, s2, o);
        if (tid == 0) g_su[b] = s2;
    }
}

// ---------------- K5: t[b,d] = sum_s u * v[b,s,d] (fp32 path) ----------------
__global__ void k5_t(const float* __restrict__ Vmat) {
    int dc = blockIdx.x, b = blockIdx.y, sc = blockIdx.z;
    int tid = threadIdx.x;
    int d = dc * 128 + tid;
    __shared__ float ush[128];
    float acc = 0.0f;
    int sbase = sc * 512;
    for (int s0 = sbase; s0 < sbase + 512; s0 += 128) {
        ush[tid] = g_u[b * SS + s0 + tid];
        __syncthreads();
        const float* base = Vmat + (size_t)(b * SS + s0) * DD + d;
#pragma unroll 8
        for (int i = 0; i < 128; i++) acc += ush[i] * base[(size_t)i * DD];
        __syncthreads();
    }
    g_t_part[(sc * BB + b) * DD + d] = acc;
}

// ---------------- K6: seed partials: t[b,:] @ Wv ----------------
__global__ void k6_seed_part(const float* __restrict__ wv_w) {
    int b = blockIdx.x, dc = blockIdx.y, j = threadIdx.x;
    __shared__ float ts[128];
    if (j < 128) {
        float s = 0.0f;
#pragma unroll
        for (int sc = 0; sc < 8; sc++) s += g_t_part[(sc * BB + b) * DD + dc * 128 + j];
        ts[j] = s;
    }
    __syncthreads();
    float acc = 0.0f;
    int dbase = dc * 128;
#pragma unroll 8
    for (int dd = 0; dd < 128; dd++)
        acc += ts[dd] * wv_w[(size_t)(dbase + dd) * KK + j];
    g_seed_part[(dc * BB + b) * KK + j] = acc;
}

// ---------------- K7: reduce + threefry noise (partitionable) ----------------
__global__ void k7_final(const float* __restrict__ wv_b, float* __restrict__ out_seed) {
    int i = blockIdx.x * 256 + threadIdx.x;
    int b = i >> 10, j = i & 1023;
    float v = 0.0f;
#pragma unroll
    for (int p = 0; p < 8; p++) v += g_seed_part[(p * BB + b) * KK + j];
    v += g_su[b] * wv_b[j];

    uint2 r = threefry2x32(0u, 1234u, 0u, (uint32_t)i);
    uint32_t bits = r.x ^ r.y;
    float f = __uint_as_float((bits >> 9) | 0x3f800000u) - 1.0f;
    const float lo = -0.99999994f;
    float u = fmaxf(lo, f * 2.0f + lo);
    float n = 1.41421356237309515f * erfinvf(u);

    out_seed[i] = v + n * 0.1f;
}

// ---------------- launch ----------------
extern "C" void kernel_launch(void* const* d_in, const int* in_sizes, int n_in,
                              void* d_out, int out_size) {
    const float* q    = (const float*)d_in[0];
    const float* kmat = (const float*)d_in[1];
    const float* vmat = (const float*)d_in[2];
    const float* wq_w = (const float*)d_in[3];
    const float* wq_b = (const float*)d_in[4];
    const float* wk_w = (const float*)d_in[5];
    const float* wk_b = (const float*)d_in[6];
    const float* wv_w = (const float*)d_in[7];
    const float* wv_b = (const float*)d_in[8];
    float* out = (float*)d_out;    // [0,8192): seed, [8192,40960): attention weights

    cudaFuncSetAttribute(k4_mma, cudaFuncAttributeMaxDynamicSharedMemorySize, K4_SMEM);

    conv_v<<<16384, 256>>>((const float4*)vmat);
    conv_wvt<<<dim3(32, 32), dim3(32, 8)>>>(wv_w);
    k1_fq_part<<<dim3(8, 8), 1024>>>(q, wq_w);
    k1b_fq_reduce<<<8, 1024>>>(wq_b, wk_b);
    k2_h<<<1024, 256>>>(wk_w);
    k3_weights<<<4096, 256>>>(kmat, out + BB * KK);
    k4_mma<<<dim3(NPART, 256), 256, K4_SMEM>>>(wv_b);
    k4b_u<<<8, 1024>>>();
    k5_t<<<dim3(8, 8, 8), 128>>>(vmat);
    k6_seed_part<<<dim3(8, 8), 1024>>>(wv_w);
    k7_final<<<32, 256>>>(wv_b, out);
}